// round 7
// baseline (speedup 1.0000x reference)
#include <cuda_runtime.h>

#define F   16
#define HID 64
#define NN  100000
#define EE  3200000
#define ROUNDS 5

typedef unsigned long long ull;

__device__ __align__(256) float g_edges[(size_t)EE * F];   // [E][F] internal layout
__device__ __align__(256) float g_nodes[F * NN];           // [F][N]
__device__ __align__(256) float g_sent[NN * F];            // [N][F]
__device__ __align__(256) float g_recv[NN * F];            // [N][F]
__device__ __align__(256) float g_ps[NN * HID];            // [N][HID]  eW1_s @ nodes + eb1
__device__ __align__(256) float g_pr[NN * HID];            // [N][HID]  eW1_r @ nodes

__device__ __forceinline__ ull pack2(float a, float b) {
    ull r; asm("mov.b64 %0, {%1,%2};" : "=l"(r) : "f"(a), "f"(b)); return r;
}
__device__ __forceinline__ void unpack2(ull v, float& a, float& b) {
    asm("mov.b64 {%0,%1}, %2;" : "=f"(a), "=f"(b) : "l"(v));
}
__device__ __forceinline__ ull fma2(ull a, ull b, ull c) {
    ull d; asm("fma.rn.f32x2 %0, %1, %2, %3;" : "=l"(d) : "l"(a), "l"(b), "l"(c)); return d;
}
__device__ __forceinline__ ull add2(ull a, ull b) {
    ull d; asm("add.rn.f32x2 %0, %1, %2;" : "=l"(d) : "l"(a), "l"(b)); return d;
}

__global__ void zero_agg_kernel() {
    int i = blockIdx.x * blockDim.x + threadIdx.x;
    const int n4 = (NN * F) / 4;
    float4 z = make_float4(0.f, 0.f, 0.f, 0.f);
    if (i < n4) {
        reinterpret_cast<float4*>(g_sent)[i] = z;
        reinterpret_cast<float4*>(g_recv)[i] = z;
    }
}

// round-0 scatter: reads the ORIGINAL [F][E] input edges
__global__ void scatter_kernel(const float* __restrict__ edges,
                               const int* __restrict__ snd, const int* __restrict__ rcv) {
    int e = blockIdx.x * blockDim.x + threadIdx.x;
    if (e >= EE) return;
    int s = snd[e];
    int r = rcv[e];
    float v[F];
#pragma unroll
    for (int f = 0; f < F; f++) v[f] = __ldcs(&edges[(size_t)f * EE + e]);
    float* ps = &g_sent[(size_t)s * F];
    float* pr = &g_recv[(size_t)r * F];
#pragma unroll
    for (int f = 0; f < F; f += 4) {
        asm volatile("red.global.add.v4.f32 [%0], {%1,%2,%3,%4};"
                     :: "l"(ps + f), "f"(v[f]), "f"(v[f + 1]), "f"(v[f + 2]), "f"(v[f + 3])
                     : "memory");
        asm volatile("red.global.add.v4.f32 [%0], {%1,%2,%3,%4};"
                     :: "l"(pr + f), "f"(v[f]), "f"(v[f + 1]), "f"(v[f + 2]), "f"(v[f + 3])
                     : "memory");
    }
}

// fused node MLP + edge projections + aggregate re-zeroing
__global__ void __launch_bounds__(256)
node_proj_kernel(const float* src_nodes_in, float* out_nodes,
                 const float* __restrict__ W1, const float* __restrict__ b1,
                 const float* __restrict__ W2, const float* __restrict__ b2,
                 const float* __restrict__ eW1, const float* __restrict__ eb1) {
    const float* __restrict__ src_nodes = src_nodes_in ? src_nodes_in : g_nodes;
    __shared__ __align__(16) float s_w1t[48 * HID];
    __shared__ __align__(16) float s_w2t[HID * F];
    __shared__ __align__(16) float s_ws[16 * HID];
    __shared__ __align__(16) float s_wr[16 * HID];
    __shared__ __align__(16) float s_b1[HID];
    __shared__ __align__(16) float s_b2[F];
    __shared__ __align__(16) float s_eb1[HID];
    for (int i = threadIdx.x; i < 48 * HID; i += blockDim.x) {
        int k = i >> 6, h = i & 63;
        s_w1t[i] = W1[h * 48 + k];
    }
    for (int i = threadIdx.x; i < HID * F; i += blockDim.x) {
        int h = i >> 4, o = i & 15;
        s_w2t[i] = W2[o * HID + h];
    }
    for (int i = threadIdx.x; i < 16 * HID; i += blockDim.x) {
        int k = i >> 6, h = i & 63;
        s_ws[i] = eW1[h * 48 + 16 + k];
        s_wr[i] = eW1[h * 48 + 32 + k];
    }
    if (threadIdx.x < HID) { s_b1[threadIdx.x] = b1[threadIdx.x]; s_eb1[threadIdx.x] = eb1[threadIdx.x]; }
    if (threadIdx.x < F)   s_b2[threadIdx.x] = b2[threadIdx.x];
    __syncthreads();

    int n = blockIdx.x * blockDim.x + threadIdx.x;
    if (n >= NN) return;

    ull acc[HID / 2];
#pragma unroll
    for (int j = 0; j < HID / 4; j++) {
        ulonglong2 bv = *reinterpret_cast<const ulonglong2*>(&s_b1[j * 4]);
        acc[2 * j] = bv.x; acc[2 * j + 1] = bv.y;
    }
#pragma unroll
    for (int k = 0; k < 16; k++) {
        float xk = src_nodes[(size_t)k * NN + n];
        ull xs = pack2(xk, xk);
        const ulonglong2* w = reinterpret_cast<const ulonglong2*>(&s_w1t[k * HID]);
#pragma unroll
        for (int m = 0; m < 16; m++) {
            ulonglong2 wv = w[m];
            acc[2 * m]     = fma2(wv.x, xs, acc[2 * m]);
            acc[2 * m + 1] = fma2(wv.y, xs, acc[2 * m + 1]);
        }
    }
    const float4 zero4 = make_float4(0.f, 0.f, 0.f, 0.f);
#pragma unroll
    for (int seg = 0; seg < 2; seg++) {
        float* aggr = seg == 0 ? &g_sent[(size_t)n * F] : &g_recv[(size_t)n * F];
        float xv[16];
#pragma unroll
        for (int q = 0; q < 4; q++) {
            float4 v = *reinterpret_cast<const float4*>(&aggr[q * 4]);
            xv[q * 4] = v.x; xv[q * 4 + 1] = v.y; xv[q * 4 + 2] = v.z; xv[q * 4 + 3] = v.w;
            // re-zero for the next round's fused scatter (this value is consumed now)
            *reinterpret_cast<float4*>(&aggr[q * 4]) = zero4;
        }
#pragma unroll
        for (int k = 0; k < 16; k++) {
            ull xs = pack2(xv[k], xv[k]);
            const ulonglong2* w = reinterpret_cast<const ulonglong2*>(&s_w1t[((seg + 1) * 16 + k) * HID]);
#pragma unroll
            for (int m = 0; m < 16; m++) {
                ulonglong2 wv = w[m];
                acc[2 * m]     = fma2(wv.x, xs, acc[2 * m]);
                acc[2 * m + 1] = fma2(wv.y, xs, acc[2 * m + 1]);
            }
        }
    }

    ull o[F / 2];
#pragma unroll
    for (int j = 0; j < 4; j++) {
        ulonglong2 bv = *reinterpret_cast<const ulonglong2*>(&s_b2[j * 4]);
        o[2 * j] = bv.x; o[2 * j + 1] = bv.y;
    }
#pragma unroll
    for (int h = 0; h < HID; h += 2) {
        float h0, h1; unpack2(acc[h >> 1], h0, h1);
        h0 = fmaxf(h0, 0.f); h1 = fmaxf(h1, 0.f);
        ull x0 = pack2(h0, h0), x1 = pack2(h1, h1);
        const ulonglong2* w0 = reinterpret_cast<const ulonglong2*>(&s_w2t[h * F]);
        const ulonglong2* w1 = reinterpret_cast<const ulonglong2*>(&s_w2t[(h + 1) * F]);
#pragma unroll
        for (int m = 0; m < 4; m++) {
            ulonglong2 a = w0[m], b = w1[m];
            o[2 * m]     = fma2(a.x, x0, o[2 * m]);
            o[2 * m]     = fma2(b.x, x1, o[2 * m]);
            o[2 * m + 1] = fma2(a.y, x0, o[2 * m + 1]);
            o[2 * m + 1] = fma2(b.y, x1, o[2 * m + 1]);
        }
    }
    float y[F];
#pragma unroll
    for (int j = 0; j < F / 2; j++) unpack2(o[j], y[2 * j], y[2 * j + 1]);
#pragma unroll
    for (int k = 0; k < F; k++) {
        g_nodes[(size_t)k * NN + n] = y[k];
    }
    if (out_nodes) {
#pragma unroll
        for (int k = 0; k < F; k++) out_nodes[(size_t)k * NN + n] = y[k];
    }

#pragma unroll
    for (int j = 0; j < HID / 4; j++) {
        ulonglong2 bv = *reinterpret_cast<const ulonglong2*>(&s_eb1[j * 4]);
        acc[2 * j] = bv.x; acc[2 * j + 1] = bv.y;
    }
#pragma unroll
    for (int k = 0; k < 16; k++) {
        ull xs = pack2(y[k], y[k]);
        const ulonglong2* w = reinterpret_cast<const ulonglong2*>(&s_ws[k * HID]);
#pragma unroll
        for (int m = 0; m < 16; m++) {
            ulonglong2 wv = w[m];
            acc[2 * m]     = fma2(wv.x, xs, acc[2 * m]);
            acc[2 * m + 1] = fma2(wv.y, xs, acc[2 * m + 1]);
        }
    }
    ull* outp = reinterpret_cast<ull*>(&g_ps[(size_t)n * HID]);
#pragma unroll
    for (int j = 0; j < HID / 2; j++) outp[j] = acc[j];

#pragma unroll
    for (int j = 0; j < HID / 2; j++) acc[j] = 0ull;
#pragma unroll
    for (int k = 0; k < 16; k++) {
        ull xs = pack2(y[k], y[k]);
        const ulonglong2* w = reinterpret_cast<const ulonglong2*>(&s_wr[k * HID]);
#pragma unroll
        for (int m = 0; m < 16; m++) {
            ulonglong2 wv = w[m];
            acc[2 * m]     = fma2(wv.x, xs, acc[2 * m]);
            acc[2 * m + 1] = fma2(wv.y, xs, acc[2 * m + 1]);
        }
    }
    outp = reinterpret_cast<ull*>(&g_pr[(size_t)n * HID]);
#pragma unroll
    for (int j = 0; j < HID / 2; j++) outp[j] = acc[j];
}

// ---------------- edge MLP v4: thread = (edge-pair, hidden-half) -------------
// Weights are reused from registers across the 2 edges of the pair, cutting
// broadcast LDS instructions per edge ~3.5x (the measured bottleneck).
#define ETPB 128
#define EPB  128
#define SG_STRIDE 68
// s_w1: [k][68], half0 h at k*68+h, half1 h at k*68+4+h (bank-offset +4)
// s_w2: half0 rows [32][16] at 0, half1 rows at 516 (=32*16+4, bank-offset +4)
#define W1_FLOATS (16 * 68)
#define W2_FLOATS (2 * 32 * 16 + 4)
#define EDGE_SMEM_FLOATS (EPB * SG_STRIDE + W1_FLOATS + W2_FLOATS + 16)

__global__ void __launch_bounds__(ETPB, 3)
edge_mlp_kernel(const float* src_fe, float* dst_fe,
                const int* __restrict__ snd, const int* __restrict__ rcv,
                const float* __restrict__ eW1, const float* __restrict__ eW2,
                const float* __restrict__ eb2, int do_scatter) {
    extern __shared__ __align__(16) float smem[];
    float* s_g  = smem;                          // EPB x 68
    float* s_w1 = smem + EPB * SG_STRIDE;        // 16 x 68
    float* s_w2 = s_w1 + W1_FLOATS;              // 1028
    float* s_b2 = s_w2 + W2_FLOATS;              // 16

    const int tid  = threadIdx.x;
    const int half = tid & 1;                    // hidden half: h in [32*half, 32*half+32)
    const int e0   = blockIdx.x * EPB;
    const int ee_l = tid & ~1;                   // even edge (local)
    const size_t ee = (size_t)e0 + ee_l;         // even edge (global)
    const size_t em = (size_t)e0 + tid;          // this thread's OUTPUT edge

    // ---- PREFETCH both edges' features (pair-threads read identical addrs ->
    //      coalescer merges, no extra traffic)
    float x0[16], x1[16];
    if (src_fe) {
#pragma unroll
        for (int k = 0; k < 16; k++) {
            x0[k] = __ldcs(&src_fe[(size_t)k * EE + ee]);
            x1[k] = __ldcs(&src_fe[(size_t)k * EE + ee + 1]);
        }
    } else {
#pragma unroll
        for (int q = 0; q < 4; q++) {
            float4 v = __ldcs(reinterpret_cast<const float4*>(&g_edges[ee * F + q * 4]));
            x0[q * 4] = v.x; x0[q * 4 + 1] = v.y; x0[q * 4 + 2] = v.z; x0[q * 4 + 3] = v.w;
            float4 u = __ldcs(reinterpret_cast<const float4*>(&g_edges[(ee + 1) * F + q * 4]));
            x1[q * 4] = u.x; x1[q * 4 + 1] = u.y; x1[q * 4 + 2] = u.z; x1[q * 4 + 3] = u.w;
        }
    }
    const int s_me = snd[em];
    const int r_me = rcv[em];

    // ---- load weights into bank-offset layouts
    for (int i = tid; i < 16 * 64; i += ETPB) {
        int k = i >> 6, h = i & 63;
        s_w1[k * 68 + h + (h >= 32 ? 4 : 0)] = eW1[h * 48 + k];
    }
    for (int i = tid; i < 64 * 16; i += ETPB) {
        int h = i >> 4, o = i & 15;
        s_w2[(h < 32) ? (h * 16 + o) : (516 + (h - 32) * 16 + o)] = eW2[o * 64 + h];
    }
    if (tid < 16) s_b2[tid] = eb2[tid];

    // ---- cooperative gather staging: s_g[el][:] = g_ps[s_el][:] + g_pr[r_el][:]
    {
        const int wid  = tid >> 5;        // 4 warps, 32 edges each
        const int lane = tid & 31;
        const int sub  = lane >> 4;
        const int c    = lane & 15;
#pragma unroll
        for (int i = 0; i < 32; i += 2) {
            int el = wid * 32 + i + sub;
            int s = snd[e0 + el];
            int r = rcv[e0 + el];
            ulonglong2 a = *reinterpret_cast<const ulonglong2*>(&g_ps[(size_t)s * HID + c * 4]);
            ulonglong2 b = *reinterpret_cast<const ulonglong2*>(&g_pr[(size_t)r * HID + c * 4]);
            ulonglong2 v; v.x = add2(a.x, b.x); v.y = add2(a.y, b.y);
            *reinterpret_cast<ulonglong2*>(&s_g[el * SG_STRIDE + c * 4]) = v;
        }
    }
    __syncthreads();

    // ---- layer-1 accumulators (my 32-h half, both edges; eb1 folded in g_ps)
    ull acc0[16], acc1[16];
    {
        const ulonglong2* g0 = reinterpret_cast<const ulonglong2*>(&s_g[ee_l * SG_STRIDE + half * 32]);
        const ulonglong2* g1 = reinterpret_cast<const ulonglong2*>(&s_g[(ee_l + 1) * SG_STRIDE + half * 32]);
#pragma unroll
        for (int m = 0; m < 8; m++) {
            ulonglong2 v = g0[m]; acc0[2 * m] = v.x; acc0[2 * m + 1] = v.y;
            ulonglong2 u = g1[m]; acc1[2 * m] = u.x; acc1[2 * m + 1] = u.y;
        }
    }

    // ---- layer 1: each weight LDS serves BOTH edges
#pragma unroll
    for (int k = 0; k < 16; k++) {
        ull xs0 = pack2(x0[k], x0[k]);
        ull xs1 = pack2(x1[k], x1[k]);
        const ulonglong2* w = reinterpret_cast<const ulonglong2*>(&s_w1[k * 68 + half * 36]);
#pragma unroll
        for (int m = 0; m < 8; m++) {
            ulonglong2 wv = w[m];
            acc0[2 * m]     = fma2(wv.x, xs0, acc0[2 * m]);
            acc0[2 * m + 1] = fma2(wv.y, xs0, acc0[2 * m + 1]);
            acc1[2 * m]     = fma2(wv.x, xs1, acc1[2 * m]);
            acc1[2 * m + 1] = fma2(wv.y, xs1, acc1[2 * m + 1]);
        }
    }

    // ---- layer 2 partials over my 32 h (bias only on half 0)
    ull o0[8], o1[8];
    if (half == 0) {
#pragma unroll
        for (int j = 0; j < 4; j++) {
            ulonglong2 bv = *reinterpret_cast<const ulonglong2*>(&s_b2[j * 4]);
            o0[2 * j] = bv.x; o0[2 * j + 1] = bv.y;
        }
#pragma unroll
        for (int j = 0; j < 8; j++) o1[j] = 0ull;
    } else {
#pragma unroll
        for (int j = 0; j < 8; j++) { o0[j] = 0ull; o1[j] = 0ull; }
    }
    const float* w2b = s_w2 + (half ? 516 : 0);
#pragma unroll
    for (int it = 0; it < 16; it++) {
        float a0, a1; unpack2(acc0[it], a0, a1);
        a0 = fmaxf(a0, 0.f); a1 = fmaxf(a1, 0.f);
        ull p00 = pack2(a0, a0), p01 = pack2(a1, a1);
        float b0, b1; unpack2(acc1[it], b0, b1);
        b0 = fmaxf(b0, 0.f); b1 = fmaxf(b1, 0.f);
        ull p10 = pack2(b0, b0), p11 = pack2(b1, b1);
        const ulonglong2* w0 = reinterpret_cast<const ulonglong2*>(&w2b[(2 * it) * 16]);
        const ulonglong2* w1 = reinterpret_cast<const ulonglong2*>(&w2b[(2 * it + 1) * 16]);
#pragma unroll
        for (int m = 0; m < 4; m++) {
            ulonglong2 a = w0[m], b = w1[m];
            o0[2 * m]     = fma2(a.x, p00, o0[2 * m]);
            o0[2 * m]     = fma2(b.x, p01, o0[2 * m]);
            o0[2 * m + 1] = fma2(a.y, p00, o0[2 * m + 1]);
            o0[2 * m + 1] = fma2(b.y, p01, o0[2 * m + 1]);
            o1[2 * m]     = fma2(a.x, p10, o1[2 * m]);
            o1[2 * m]     = fma2(b.x, p11, o1[2 * m]);
            o1[2 * m + 1] = fma2(a.y, p10, o1[2 * m + 1]);
            o1[2 * m + 1] = fma2(b.y, p11, o1[2 * m + 1]);
        }
    }

    // ---- combine hidden halves across the thread pair (lane ^ 1)
    float ov0[16], ov1[16];
#pragma unroll
    for (int j = 0; j < 8; j++) {
        unpack2(o0[j], ov0[2 * j], ov0[2 * j + 1]);
        unpack2(o1[j], ov1[2 * j], ov1[2 * j + 1]);
    }
#pragma unroll
    for (int f = 0; f < 16; f++) {
        ov0[f] += __shfl_xor_sync(0xFFFFFFFFu, ov0[f], 1);
        ov1[f] += __shfl_xor_sync(0xFFFFFFFFu, ov1[f], 1);
    }
    float ov[16];
#pragma unroll
    for (int f = 0; f < 16; f++) ov[f] = half ? ov1[f] : ov0[f];

    // ---- write my edge's new features
    if (dst_fe) {
#pragma unroll
        for (int f = 0; f < F; f++) __stcs(&dst_fe[(size_t)f * EE + em], ov[f]);
    } else {
#pragma unroll
        for (int q = 0; q < 4; q++) {
            float4 v = make_float4(ov[q * 4], ov[q * 4 + 1], ov[q * 4 + 2], ov[q * 4 + 3]);
            __stcs(reinterpret_cast<float4*>(&g_edges[em * F + q * 4]), v);
        }
    }

    // ---- fused scatter into next round's aggregates
    if (do_scatter) {
        float* ps = &g_sent[(size_t)s_me * F];
        float* pr = &g_recv[(size_t)r_me * F];
#pragma unroll
        for (int f = 0; f < F; f += 4) {
            asm volatile("red.global.add.v4.f32 [%0], {%1,%2,%3,%4};"
                         :: "l"(ps + f), "f"(ov[f]), "f"(ov[f + 1]), "f"(ov[f + 2]), "f"(ov[f + 3])
                         : "memory");
            asm volatile("red.global.add.v4.f32 [%0], {%1,%2,%3,%4};"
                         :: "l"(pr + f), "f"(ov[f]), "f"(ov[f + 1]), "f"(ov[f + 2]), "f"(ov[f + 3])
                         : "memory");
        }
    }
}

extern "C" void kernel_launch(void* const* d_in, const int* in_sizes, int n_in,
                              void* d_out, int out_size) {
    const float* nodes     = (const float*)d_in[0];
    const float* edges     = (const float*)d_in[1];
    const int*   receivers = (const int*)  d_in[2];
    const int*   senders   = (const int*)  d_in[3];
    const float* nW1 = (const float*)d_in[4];
    const float* nb1 = (const float*)d_in[5];
    const float* nW2 = (const float*)d_in[6];
    const float* nb2 = (const float*)d_in[7];
    const float* eW1 = (const float*)d_in[8];
    const float* eb1 = (const float*)d_in[9];
    const float* eW2 = (const float*)d_in[10];
    const float* eb2 = (const float*)d_in[11];
    float* out_nodes = (float*)d_out;
    float* out_edges = (float*)d_out + (size_t)F * NN;

    const int EDGE_BLOCKS = EE / EPB;                  // 25000
    const int NODE_BLOCKS = (NN + 255) / 256;          // 391
    const int ZERO_BLOCKS = ((NN * F) / 4 + 255) / 256;
    const int EDGE_SMEM = EDGE_SMEM_FLOATS * 4;        // ~43.3 KB

    static int configured = 0;
    if (!configured) {
        cudaFuncSetAttribute(edge_mlp_kernel, cudaFuncAttributeMaxDynamicSharedMemorySize, EDGE_SMEM);
        configured = 1;
    }

    zero_agg_kernel<<<ZERO_BLOCKS, 256>>>();
    scatter_kernel<<<(EE + 255) / 256, 256>>>(edges, senders, receivers);

    for (int round = 0; round < ROUNDS; round++) {
        node_proj_kernel<<<NODE_BLOCKS, 256>>>(
            (round == 0) ? nodes : (const float*)0,
            (round == ROUNDS - 1) ? out_nodes : (float*)0,
            nW1, nb1, nW2, nb2, eW1, eb1);
        edge_mlp_kernel<<<EDGE_BLOCKS, ETPB, EDGE_SMEM>>>(
            (round == 0) ? edges : (const float*)0,
            (round == ROUNDS - 1) ? out_edges : (float*)0,
            senders, receivers, eW1, eW2, eb2, (round < ROUNDS - 1) ? 1 : 0);
    }
}

// round 8
// speedup vs baseline: 1.6630x; 1.6630x over previous
#include <cuda_runtime.h>

#define F   16
#define HID 64
#define NN  100000
#define EE  3200000
#define ROUNDS 5

typedef unsigned long long ull;

__device__ __align__(256) float g_edges[(size_t)EE * F];   // [E][F] internal layout
__device__ __align__(256) float g_nodes[F * NN];           // [F][N]
__device__ __align__(256) float g_sent[NN * F];            // [N][F]
__device__ __align__(256) float g_recv[NN * F];            // [N][F]
__device__ __align__(256) float g_ps[NN * HID];            // [N][HID]  eW1_s @ nodes + eb1
__device__ __align__(256) float g_pr[NN * HID];            // [N][HID]  eW1_r @ nodes

__device__ __forceinline__ ull pack2(float a, float b) {
    ull r; asm("mov.b64 %0, {%1,%2};" : "=l"(r) : "f"(a), "f"(b)); return r;
}
__device__ __forceinline__ void unpack2(ull v, float& a, float& b) {
    asm("mov.b64 {%0,%1}, %2;" : "=f"(a), "=f"(b) : "l"(v));
}
__device__ __forceinline__ ull fma2(ull a, ull b, ull c) {
    ull d; asm("fma.rn.f32x2 %0, %1, %2, %3;" : "=l"(d) : "l"(a), "l"(b), "l"(c)); return d;
}
__device__ __forceinline__ ull add2(ull a, ull b) {
    ull d; asm("add.rn.f32x2 %0, %1, %2;" : "=l"(d) : "l"(a), "l"(b)); return d;
}

__global__ void zero_agg_kernel() {
    int i = blockIdx.x * blockDim.x + threadIdx.x;
    const int n4 = (NN * F) / 4;
    float4 z = make_float4(0.f, 0.f, 0.f, 0.f);
    if (i < n4) {
        reinterpret_cast<float4*>(g_sent)[i] = z;
        reinterpret_cast<float4*>(g_recv)[i] = z;
    }
}

// round-0 scatter: reads the ORIGINAL [F][E] input edges
__global__ void scatter_kernel(const float* __restrict__ edges,
                               const int* __restrict__ snd, const int* __restrict__ rcv) {
    int e = blockIdx.x * blockDim.x + threadIdx.x;
    if (e >= EE) return;
    int s = snd[e];
    int r = rcv[e];
    float v[F];
#pragma unroll
    for (int f = 0; f < F; f++) v[f] = __ldcs(&edges[(size_t)f * EE + e]);
    float* ps = &g_sent[(size_t)s * F];
    float* pr = &g_recv[(size_t)r * F];
#pragma unroll
    for (int f = 0; f < F; f += 4) {
        asm volatile("red.global.add.v4.f32 [%0], {%1,%2,%3,%4};"
                     :: "l"(ps + f), "f"(v[f]), "f"(v[f + 1]), "f"(v[f + 2]), "f"(v[f + 3])
                     : "memory");
        asm volatile("red.global.add.v4.f32 [%0], {%1,%2,%3,%4};"
                     :: "l"(pr + f), "f"(v[f]), "f"(v[f + 1]), "f"(v[f + 2]), "f"(v[f + 3])
                     : "memory");
    }
}

// fused node MLP + edge projections + aggregate re-zeroing
__global__ void __launch_bounds__(256)
node_proj_kernel(const float* src_nodes_in, float* out_nodes,
                 const float* __restrict__ W1, const float* __restrict__ b1,
                 const float* __restrict__ W2, const float* __restrict__ b2,
                 const float* __restrict__ eW1, const float* __restrict__ eb1) {
    const float* __restrict__ src_nodes = src_nodes_in ? src_nodes_in : g_nodes;
    __shared__ __align__(16) float s_w1t[48 * HID];
    __shared__ __align__(16) float s_w2t[HID * F];
    __shared__ __align__(16) float s_ws[16 * HID];
    __shared__ __align__(16) float s_wr[16 * HID];
    __shared__ __align__(16) float s_b1[HID];
    __shared__ __align__(16) float s_b2[F];
    __shared__ __align__(16) float s_eb1[HID];
    for (int i = threadIdx.x; i < 48 * HID; i += blockDim.x) {
        int k = i >> 6, h = i & 63;
        s_w1t[i] = W1[h * 48 + k];
    }
    for (int i = threadIdx.x; i < HID * F; i += blockDim.x) {
        int h = i >> 4, o = i & 15;
        s_w2t[i] = W2[o * HID + h];
    }
    for (int i = threadIdx.x; i < 16 * HID; i += blockDim.x) {
        int k = i >> 6, h = i & 63;
        s_ws[i] = eW1[h * 48 + 16 + k];
        s_wr[i] = eW1[h * 48 + 32 + k];
    }
    if (threadIdx.x < HID) { s_b1[threadIdx.x] = b1[threadIdx.x]; s_eb1[threadIdx.x] = eb1[threadIdx.x]; }
    if (threadIdx.x < F)   s_b2[threadIdx.x] = b2[threadIdx.x];
    __syncthreads();

    int n = blockIdx.x * blockDim.x + threadIdx.x;
    if (n >= NN) return;

    ull acc[HID / 2];
#pragma unroll
    for (int j = 0; j < HID / 4; j++) {
        ulonglong2 bv = *reinterpret_cast<const ulonglong2*>(&s_b1[j * 4]);
        acc[2 * j] = bv.x; acc[2 * j + 1] = bv.y;
    }
#pragma unroll
    for (int k = 0; k < 16; k++) {
        float xk = src_nodes[(size_t)k * NN + n];
        ull xs = pack2(xk, xk);
        const ulonglong2* w = reinterpret_cast<const ulonglong2*>(&s_w1t[k * HID]);
#pragma unroll
        for (int m = 0; m < 16; m++) {
            ulonglong2 wv = w[m];
            acc[2 * m]     = fma2(wv.x, xs, acc[2 * m]);
            acc[2 * m + 1] = fma2(wv.y, xs, acc[2 * m + 1]);
        }
    }
    const float4 zero4 = make_float4(0.f, 0.f, 0.f, 0.f);
#pragma unroll
    for (int seg = 0; seg < 2; seg++) {
        float* aggr = seg == 0 ? &g_sent[(size_t)n * F] : &g_recv[(size_t)n * F];
        float xv[16];
#pragma unroll
        for (int q = 0; q < 4; q++) {
            float4 v = *reinterpret_cast<const float4*>(&aggr[q * 4]);
            xv[q * 4] = v.x; xv[q * 4 + 1] = v.y; xv[q * 4 + 2] = v.z; xv[q * 4 + 3] = v.w;
            *reinterpret_cast<float4*>(&aggr[q * 4]) = zero4;  // re-zero for next round
        }
#pragma unroll
        for (int k = 0; k < 16; k++) {
            ull xs = pack2(xv[k], xv[k]);
            const ulonglong2* w = reinterpret_cast<const ulonglong2*>(&s_w1t[((seg + 1) * 16 + k) * HID]);
#pragma unroll
            for (int m = 0; m < 16; m++) {
                ulonglong2 wv = w[m];
                acc[2 * m]     = fma2(wv.x, xs, acc[2 * m]);
                acc[2 * m + 1] = fma2(wv.y, xs, acc[2 * m + 1]);
            }
        }
    }

    ull o[F / 2];
#pragma unroll
    for (int j = 0; j < 4; j++) {
        ulonglong2 bv = *reinterpret_cast<const ulonglong2*>(&s_b2[j * 4]);
        o[2 * j] = bv.x; o[2 * j + 1] = bv.y;
    }
#pragma unroll
    for (int h = 0; h < HID; h += 2) {
        float h0, h1; unpack2(acc[h >> 1], h0, h1);
        h0 = fmaxf(h0, 0.f); h1 = fmaxf(h1, 0.f);
        ull x0 = pack2(h0, h0), x1 = pack2(h1, h1);
        const ulonglong2* w0 = reinterpret_cast<const ulonglong2*>(&s_w2t[h * F]);
        const ulonglong2* w1 = reinterpret_cast<const ulonglong2*>(&s_w2t[(h + 1) * F]);
#pragma unroll
        for (int m = 0; m < 4; m++) {
            ulonglong2 a = w0[m], b = w1[m];
            o[2 * m]     = fma2(a.x, x0, o[2 * m]);
            o[2 * m]     = fma2(b.x, x1, o[2 * m]);
            o[2 * m + 1] = fma2(a.y, x0, o[2 * m + 1]);
            o[2 * m + 1] = fma2(b.y, x1, o[2 * m + 1]);
        }
    }
    float y[F];
#pragma unroll
    for (int j = 0; j < F / 2; j++) unpack2(o[j], y[2 * j], y[2 * j + 1]);
#pragma unroll
    for (int k = 0; k < F; k++) {
        g_nodes[(size_t)k * NN + n] = y[k];
    }
    if (out_nodes) {
#pragma unroll
        for (int k = 0; k < F; k++) out_nodes[(size_t)k * NN + n] = y[k];
    }

#pragma unroll
    for (int j = 0; j < HID / 4; j++) {
        ulonglong2 bv = *reinterpret_cast<const ulonglong2*>(&s_eb1[j * 4]);
        acc[2 * j] = bv.x; acc[2 * j + 1] = bv.y;
    }
#pragma unroll
    for (int k = 0; k < 16; k++) {
        ull xs = pack2(y[k], y[k]);
        const ulonglong2* w = reinterpret_cast<const ulonglong2*>(&s_ws[k * HID]);
#pragma unroll
        for (int m = 0; m < 16; m++) {
            ulonglong2 wv = w[m];
            acc[2 * m]     = fma2(wv.x, xs, acc[2 * m]);
            acc[2 * m + 1] = fma2(wv.y, xs, acc[2 * m + 1]);
        }
    }
    ull* outp = reinterpret_cast<ull*>(&g_ps[(size_t)n * HID]);
#pragma unroll
    for (int j = 0; j < HID / 2; j++) outp[j] = acc[j];

#pragma unroll
    for (int j = 0; j < HID / 2; j++) acc[j] = 0ull;
#pragma unroll
    for (int k = 0; k < 16; k++) {
        ull xs = pack2(y[k], y[k]);
        const ulonglong2* w = reinterpret_cast<const ulonglong2*>(&s_wr[k * HID]);
#pragma unroll
        for (int m = 0; m < 16; m++) {
            ulonglong2 wv = w[m];
            acc[2 * m]     = fma2(wv.x, xs, acc[2 * m]);
            acc[2 * m + 1] = fma2(wv.y, xs, acc[2 * m + 1]);
        }
    }
    outp = reinterpret_cast<ull*>(&g_pr[(size_t)n * HID]);
#pragma unroll
    for (int j = 0; j < HID / 2; j++) outp[j] = acc[j];
}

// ---------------- edge MLP v5: pair-split, smem-staged x, fixed banking ------
#define ETPB 128
#define EPB  128
#define SG_STRIDE 68   // gather row: halves at +0 / +36 (pad 32..35)
#define SX_STRIDE 34   // x row per PAIR: [k*2 + half]
#define SG_FLOATS (EPB * SG_STRIDE)
#define SX_FLOATS ((EPB / 2) * SX_STRIDE)
#define W1_FLOATS (16 * 68)
#define W2_FLOATS (2 * 32 * 16 + 4)
#define EDGE_SMEM_FLOATS (SG_FLOATS + SX_FLOATS + W1_FLOATS + W2_FLOATS + 16)

__global__ void __launch_bounds__(ETPB, 3)
edge_mlp_kernel(const float* src_fe, float* dst_fe,
                const int* __restrict__ snd, const int* __restrict__ rcv,
                const float* __restrict__ eW1, const float* __restrict__ eW2,
                const float* __restrict__ eb2, int do_scatter) {
    extern __shared__ __align__(16) float smem[];
    float* s_g  = smem;                          // EPB x 68 (split halves)
    float* s_x  = s_g + SG_FLOATS;               // (EPB/2) x 34
    float* s_w1 = s_x + SX_FLOATS;               // 16 x 68 (split halves)
    float* s_w2 = s_w1 + W1_FLOATS;              // 1028 (split at 516)
    float* s_b2 = s_w2 + W2_FLOATS;              // 16

    const int tid  = threadIdx.x;
    const int half = tid & 1;                    // hidden half: h in [32*half, 32*half+32)
    const int pair = tid >> 1;                   // local pair index
    const int e0   = blockIdx.x * EPB;
    const int ee_l = tid & ~1;                   // even local edge of my pair
    const size_t em = (size_t)e0 + tid;          // my OUTPUT edge

    // ---- load my edge's features (coalesced) + indices, stage x into smem
    float x[16];
    if (src_fe) {
#pragma unroll
        for (int k = 0; k < 16; k++) x[k] = __ldcs(&src_fe[(size_t)k * EE + em]);
    } else {
#pragma unroll
        for (int q = 0; q < 4; q++) {
            float4 v = __ldcs(reinterpret_cast<const float4*>(&g_edges[em * F + q * 4]));
            x[q * 4] = v.x; x[q * 4 + 1] = v.y; x[q * 4 + 2] = v.z; x[q * 4 + 3] = v.w;
        }
    }
    const int s_me = snd[em];
    const int r_me = rcv[em];
#pragma unroll
    for (int k = 0; k < 16; k++) s_x[pair * SX_STRIDE + 2 * k + half] = x[k];

    // ---- load weights into split layouts
    for (int i = tid; i < 16 * 64; i += ETPB) {
        int k = i >> 6, h = i & 63;
        s_w1[k * 68 + h + (h >= 32 ? 4 : 0)] = eW1[h * 48 + k];
    }
    for (int i = tid; i < 64 * 16; i += ETPB) {
        int h = i >> 4, o = i & 15;
        s_w2[(h < 32) ? (h * 16 + o) : (516 + (h - 32) * 16 + o)] = eW2[o * 64 + h];
    }
    if (tid < 16) s_b2[tid] = eb2[tid];

    // ---- cooperative gather staging into split rows:
    //      chunk c (16B) -> word offset c*4 + (c>=8 ? 4 : 0)
    {
        const int wid  = tid >> 5;        // 4 warps, 32 edges each
        const int lane = tid & 31;
        const int sub  = lane >> 4;
        const int c    = lane & 15;
        const int coff = c * 4 + (c >= 8 ? 4 : 0);
#pragma unroll
        for (int i = 0; i < 32; i += 2) {
            int el = wid * 32 + i + sub;
            int s = snd[e0 + el];
            int r = rcv[e0 + el];
            ulonglong2 a = *reinterpret_cast<const ulonglong2*>(&g_ps[(size_t)s * HID + c * 4]);
            ulonglong2 b = *reinterpret_cast<const ulonglong2*>(&g_pr[(size_t)r * HID + c * 4]);
            ulonglong2 v; v.x = add2(a.x, b.x); v.y = add2(a.y, b.y);
            *reinterpret_cast<ulonglong2*>(&s_g[el * SG_STRIDE + coff]) = v;
        }
    }
    __syncthreads();

    // ---- layer-1 accumulators: my half of BOTH edges (eb1 folded in g_ps)
    ull acc0[16], acc1[16];   // acc0: edge ee_l, acc1: edge ee_l+1
    {
        const ulonglong2* g0 = reinterpret_cast<const ulonglong2*>(&s_g[ee_l * SG_STRIDE + half * 36]);
        const ulonglong2* g1 = reinterpret_cast<const ulonglong2*>(&s_g[(ee_l + 1) * SG_STRIDE + half * 36]);
#pragma unroll
        for (int m = 0; m < 8; m++) {
            ulonglong2 v = g0[m]; acc0[2 * m] = v.x; acc0[2 * m + 1] = v.y;
            ulonglong2 u = g1[m]; acc1[2 * m] = u.x; acc1[2 * m + 1] = u.y;
        }
    }

    // ---- layer 1: one LDS.64 per k gives both edges' x; weights shared
#pragma unroll
    for (int k = 0; k < 16; k++) {
        float2 xp = *reinterpret_cast<const float2*>(&s_x[pair * SX_STRIDE + 2 * k]);
        ull xs0 = pack2(xp.x, xp.x);     // edge ee_l
        ull xs1 = pack2(xp.y, xp.y);     // edge ee_l+1
        const ulonglong2* w = reinterpret_cast<const ulonglong2*>(&s_w1[k * 68 + half * 36]);
#pragma unroll
        for (int m = 0; m < 8; m++) {
            ulonglong2 wv = w[m];
            acc0[2 * m]     = fma2(wv.x, xs0, acc0[2 * m]);
            acc0[2 * m + 1] = fma2(wv.y, xs0, acc0[2 * m + 1]);
            acc1[2 * m]     = fma2(wv.x, xs1, acc1[2 * m]);
            acc1[2 * m + 1] = fma2(wv.y, xs1, acc1[2 * m + 1]);
        }
    }

    // ---- layer 2 partials over my 32 h (half 0 carries bias for BOTH edges)
    ull o0[8], o1[8];
    if (half == 0) {
#pragma unroll
        for (int j = 0; j < 4; j++) {
            ulonglong2 bv = *reinterpret_cast<const ulonglong2*>(&s_b2[j * 4]);
            o0[2 * j] = bv.x; o0[2 * j + 1] = bv.y;
            o1[2 * j] = bv.x; o1[2 * j + 1] = bv.y;
        }
    } else {
#pragma unroll
        for (int j = 0; j < 8; j++) { o0[j] = 0ull; o1[j] = 0ull; }
    }
    const float* w2b = s_w2 + (half ? 516 : 0);
#pragma unroll
    for (int it = 0; it < 16; it++) {
        float a0, a1; unpack2(acc0[it], a0, a1);
        a0 = fmaxf(a0, 0.f); a1 = fmaxf(a1, 0.f);
        ull p00 = pack2(a0, a0), p01 = pack2(a1, a1);
        float b0, b1; unpack2(acc1[it], b0, b1);
        b0 = fmaxf(b0, 0.f); b1 = fmaxf(b1, 0.f);
        ull p10 = pack2(b0, b0), p11 = pack2(b1, b1);
        const ulonglong2* w0 = reinterpret_cast<const ulonglong2*>(&w2b[(2 * it) * 16]);
        const ulonglong2* w1 = reinterpret_cast<const ulonglong2*>(&w2b[(2 * it + 1) * 16]);
#pragma unroll
        for (int m = 0; m < 4; m++) {
            ulonglong2 a = w0[m], b = w1[m];
            o0[2 * m]     = fma2(a.x, p00, o0[2 * m]);
            o0[2 * m]     = fma2(b.x, p01, o0[2 * m]);
            o0[2 * m + 1] = fma2(a.y, p00, o0[2 * m + 1]);
            o0[2 * m + 1] = fma2(b.y, p01, o0[2 * m + 1]);
            o1[2 * m]     = fma2(a.x, p10, o1[2 * m]);
            o1[2 * m]     = fma2(b.x, p11, o1[2 * m]);
            o1[2 * m + 1] = fma2(a.y, p10, o1[2 * m + 1]);
            o1[2 * m + 1] = fma2(b.y, p11, o1[2 * m + 1]);
        }
    }

    // ---- single exchange: send partner's-edge partial, receive mine
    float ov[16];
#pragma unroll
    for (int j = 0; j < 8; j++) {
        ull sel  = half ? o0[j] : o1[j];            // partial for PARTNER's edge
        ull rec  = __shfl_xor_sync(0xFFFFFFFFu, sel, 1);
        ull mine = half ? o1[j] : o0[j];            // my partial for MY edge
        ull tot  = add2(mine, rec);
        unpack2(tot, ov[2 * j], ov[2 * j + 1]);
    }

    // ---- write my edge's new features
    if (dst_fe) {
#pragma unroll
        for (int f = 0; f < F; f++) __stcs(&dst_fe[(size_t)f * EE + em], ov[f]);
    } else {
#pragma unroll
        for (int q = 0; q < 4; q++) {
            float4 v = make_float4(ov[q * 4], ov[q * 4 + 1], ov[q * 4 + 2], ov[q * 4 + 3]);
            __stcs(reinterpret_cast<float4*>(&g_edges[em * F + q * 4]), v);
        }
    }

    // ---- fused scatter into next round's aggregates
    if (do_scatter) {
        float* ps = &g_sent[(size_t)s_me * F];
        float* pr = &g_recv[(size_t)r_me * F];
#pragma unroll
        for (int f = 0; f < F; f += 4) {
            asm volatile("red.global.add.v4.f32 [%0], {%1,%2,%3,%4};"
                         :: "l"(ps + f), "f"(ov[f]), "f"(ov[f + 1]), "f"(ov[f + 2]), "f"(ov[f + 3])
                         : "memory");
            asm volatile("red.global.add.v4.f32 [%0], {%1,%2,%3,%4};"
                         :: "l"(pr + f), "f"(ov[f]), "f"(ov[f + 1]), "f"(ov[f + 2]), "f"(ov[f + 3])
                         : "memory");
        }
    }
}

extern "C" void kernel_launch(void* const* d_in, const int* in_sizes, int n_in,
                              void* d_out, int out_size) {
    const float* nodes     = (const float*)d_in[0];
    const float* edges     = (const float*)d_in[1];
    const int*   receivers = (const int*)  d_in[2];
    const int*   senders   = (const int*)  d_in[3];
    const float* nW1 = (const float*)d_in[4];
    const float* nb1 = (const float*)d_in[5];
    const float* nW2 = (const float*)d_in[6];
    const float* nb2 = (const float*)d_in[7];
    const float* eW1 = (const float*)d_in[8];
    const float* eb1 = (const float*)d_in[9];
    const float* eW2 = (const float*)d_in[10];
    const float* eb2 = (const float*)d_in[11];
    float* out_nodes = (float*)d_out;
    float* out_edges = (float*)d_out + (size_t)F * NN;

    const int EDGE_BLOCKS = EE / EPB;                  // 25000
    const int NODE_BLOCKS = (NN + 255) / 256;          // 391
    const int ZERO_BLOCKS = ((NN * F) / 4 + 255) / 256;
    const int EDGE_SMEM = EDGE_SMEM_FLOATS * 4;        // ~52 KB

    static int configured = 0;
    if (!configured) {
        cudaFuncSetAttribute(edge_mlp_kernel, cudaFuncAttributeMaxDynamicSharedMemorySize, EDGE_SMEM);
        configured = 1;
    }

    zero_agg_kernel<<<ZERO_BLOCKS, 256>>>();
    scatter_kernel<<<(EE + 255) / 256, 256>>>(edges, senders, receivers);

    for (int round = 0; round < ROUNDS; round++) {
        node_proj_kernel<<<NODE_BLOCKS, 256>>>(
            (round == 0) ? nodes : (const float*)0,
            (round == ROUNDS - 1) ? out_nodes : (float*)0,
            nW1, nb1, nW2, nb2, eW1, eb1);
        edge_mlp_kernel<<<EDGE_BLOCKS, ETPB, EDGE_SMEM>>>(
            (round == 0) ? edges : (const float*)0,
            (round == ROUNDS - 1) ? out_edges : (float*)0,
            senders, receivers, eW1, eW2, eb2, (round < ROUNDS - 1) ? 1 : 0);
    }
}

// round 9
// speedup vs baseline: 1.8941x; 1.1390x over previous
#include <cuda_runtime.h>

#define F   16
#define HID 64
#define NN  100000
#define EE  3200000
#define ROUNDS 5

typedef unsigned long long ull;

__device__ __align__(256) float g_edges[(size_t)EE * F];   // [E][F] internal layout
__device__ __align__(256) float g_nodes[F * NN];           // [F][N]
__device__ __align__(256) float g_sent[NN * F];            // [N][F]
__device__ __align__(256) float g_recv[NN * F];            // [N][F]
__device__ __align__(256) float g_ps[NN * HID];            // [N][HID]  eW1_s @ nodes + eb1
__device__ __align__(256) float g_pr[NN * HID];            // [N][HID]  eW1_r @ nodes

// pre-transposed edge-MLP weights (smem-layout-identical, loaded linearly)
#define W1_FLOATS (16 * 68)            // [k][68]: half0 h at k*68+h, half1 at k*68+4+h
#define W2_FLOATS (2 * 32 * 16 + 4)    // half0 rows at 0, half1 rows at 516
__device__ __align__(256) float g_w1p[W1_FLOATS];
__device__ __align__(256) float g_w2p[W2_FLOATS];
__device__ __align__(256) float g_b2p[16];

__device__ __forceinline__ ull pack2(float a, float b) {
    ull r; asm("mov.b64 %0, {%1,%2};" : "=l"(r) : "f"(a), "f"(b)); return r;
}
__device__ __forceinline__ void unpack2(ull v, float& a, float& b) {
    asm("mov.b64 {%0,%1}, %2;" : "=f"(a), "=f"(b) : "l"(v));
}
__device__ __forceinline__ ull fma2(ull a, ull b, ull c) {
    ull d; asm("fma.rn.f32x2 %0, %1, %2, %3;" : "=l"(d) : "l"(a), "l"(b), "l"(c)); return d;
}
__device__ __forceinline__ ull add2(ull a, ull b) {
    ull d; asm("add.rn.f32x2 %0, %1, %2;" : "=l"(d) : "l"(a), "l"(b)); return d;
}

// one-time: transpose edge weights into the edge kernel's smem layout
__global__ void prep_weights_kernel(const float* __restrict__ eW1,
                                    const float* __restrict__ eW2,
                                    const float* __restrict__ eb2) {
    int tid = threadIdx.x;
    for (int i = tid; i < 16 * 64; i += blockDim.x) {
        int k = i >> 6, h = i & 63;
        g_w1p[k * 68 + h + (h >= 32 ? 4 : 0)] = eW1[h * 48 + k];
    }
    for (int i = tid; i < 64 * 16; i += blockDim.x) {
        int h = i >> 4, o = i & 15;
        g_w2p[(h < 32) ? (h * 16 + o) : (516 + (h - 32) * 16 + o)] = eW2[o * 64 + h];
    }
    if (tid < 16) g_b2p[tid] = eb2[tid];
}

__global__ void zero_agg_kernel() {
    int i = blockIdx.x * blockDim.x + threadIdx.x;
    const int n4 = (NN * F) / 4;
    float4 z = make_float4(0.f, 0.f, 0.f, 0.f);
    if (i < n4) {
        reinterpret_cast<float4*>(g_sent)[i] = z;
        reinterpret_cast<float4*>(g_recv)[i] = z;
    }
}

// round-0 scatter: reads the ORIGINAL [F][E] input edges
__global__ void scatter_kernel(const float* __restrict__ edges,
                               const int* __restrict__ snd, const int* __restrict__ rcv) {
    int e = blockIdx.x * blockDim.x + threadIdx.x;
    if (e >= EE) return;
    int s = snd[e];
    int r = rcv[e];
    float v[F];
#pragma unroll
    for (int f = 0; f < F; f++) v[f] = __ldcs(&edges[(size_t)f * EE + e]);
    float* ps = &g_sent[(size_t)s * F];
    float* pr = &g_recv[(size_t)r * F];
#pragma unroll
    for (int f = 0; f < F; f += 4) {
        asm volatile("red.global.add.v4.f32 [%0], {%1,%2,%3,%4};"
                     :: "l"(ps + f), "f"(v[f]), "f"(v[f + 1]), "f"(v[f + 2]), "f"(v[f + 3])
                     : "memory");
        asm volatile("red.global.add.v4.f32 [%0], {%1,%2,%3,%4};"
                     :: "l"(pr + f), "f"(v[f]), "f"(v[f + 1]), "f"(v[f + 2]), "f"(v[f + 3])
                     : "memory");
    }
}

// fused node MLP + edge projections + aggregate re-zeroing (unchanged)
__global__ void __launch_bounds__(256)
node_proj_kernel(const float* src_nodes_in, float* out_nodes,
                 const float* __restrict__ W1, const float* __restrict__ b1,
                 const float* __restrict__ W2, const float* __restrict__ b2,
                 const float* __restrict__ eW1, const float* __restrict__ eb1) {
    const float* __restrict__ src_nodes = src_nodes_in ? src_nodes_in : g_nodes;
    __shared__ __align__(16) float s_w1t[48 * HID];
    __shared__ __align__(16) float s_w2t[HID * F];
    __shared__ __align__(16) float s_ws[16 * HID];
    __shared__ __align__(16) float s_wr[16 * HID];
    __shared__ __align__(16) float s_b1[HID];
    __shared__ __align__(16) float s_b2[F];
    __shared__ __align__(16) float s_eb1[HID];
    for (int i = threadIdx.x; i < 48 * HID; i += blockDim.x) {
        int k = i >> 6, h = i & 63;
        s_w1t[i] = W1[h * 48 + k];
    }
    for (int i = threadIdx.x; i < HID * F; i += blockDim.x) {
        int h = i >> 4, o = i & 15;
        s_w2t[i] = W2[o * HID + h];
    }
    for (int i = threadIdx.x; i < 16 * HID; i += blockDim.x) {
        int k = i >> 6, h = i & 63;
        s_ws[i] = eW1[h * 48 + 16 + k];
        s_wr[i] = eW1[h * 48 + 32 + k];
    }
    if (threadIdx.x < HID) { s_b1[threadIdx.x] = b1[threadIdx.x]; s_eb1[threadIdx.x] = eb1[threadIdx.x]; }
    if (threadIdx.x < F)   s_b2[threadIdx.x] = b2[threadIdx.x];
    __syncthreads();

    int n = blockIdx.x * blockDim.x + threadIdx.x;
    if (n >= NN) return;

    ull acc[HID / 2];
#pragma unroll
    for (int j = 0; j < HID / 4; j++) {
        ulonglong2 bv = *reinterpret_cast<const ulonglong2*>(&s_b1[j * 4]);
        acc[2 * j] = bv.x; acc[2 * j + 1] = bv.y;
    }
#pragma unroll
    for (int k = 0; k < 16; k++) {
        float xk = src_nodes[(size_t)k * NN + n];
        ull xs = pack2(xk, xk);
        const ulonglong2* w = reinterpret_cast<const ulonglong2*>(&s_w1t[k * HID]);
#pragma unroll
        for (int m = 0; m < 16; m++) {
            ulonglong2 wv = w[m];
            acc[2 * m]     = fma2(wv.x, xs, acc[2 * m]);
            acc[2 * m + 1] = fma2(wv.y, xs, acc[2 * m + 1]);
        }
    }
    const float4 zero4 = make_float4(0.f, 0.f, 0.f, 0.f);
#pragma unroll
    for (int seg = 0; seg < 2; seg++) {
        float* aggr = seg == 0 ? &g_sent[(size_t)n * F] : &g_recv[(size_t)n * F];
        float xv[16];
#pragma unroll
        for (int q = 0; q < 4; q++) {
            float4 v = *reinterpret_cast<const float4*>(&aggr[q * 4]);
            xv[q * 4] = v.x; xv[q * 4 + 1] = v.y; xv[q * 4 + 2] = v.z; xv[q * 4 + 3] = v.w;
            *reinterpret_cast<float4*>(&aggr[q * 4]) = zero4;  // re-zero for next round
        }
#pragma unroll
        for (int k = 0; k < 16; k++) {
            ull xs = pack2(xv[k], xv[k]);
            const ulonglong2* w = reinterpret_cast<const ulonglong2*>(&s_w1t[((seg + 1) * 16 + k) * HID]);
#pragma unroll
            for (int m = 0; m < 16; m++) {
                ulonglong2 wv = w[m];
                acc[2 * m]     = fma2(wv.x, xs, acc[2 * m]);
                acc[2 * m + 1] = fma2(wv.y, xs, acc[2 * m + 1]);
            }
        }
    }

    ull o[F / 2];
#pragma unroll
    for (int j = 0; j < 4; j++) {
        ulonglong2 bv = *reinterpret_cast<const ulonglong2*>(&s_b2[j * 4]);
        o[2 * j] = bv.x; o[2 * j + 1] = bv.y;
    }
#pragma unroll
    for (int h = 0; h < HID; h += 2) {
        float h0, h1; unpack2(acc[h >> 1], h0, h1);
        h0 = fmaxf(h0, 0.f); h1 = fmaxf(h1, 0.f);
        ull x0 = pack2(h0, h0), x1 = pack2(h1, h1);
        const ulonglong2* w0 = reinterpret_cast<const ulonglong2*>(&s_w2t[h * F]);
        const ulonglong2* w1 = reinterpret_cast<const ulonglong2*>(&s_w2t[(h + 1) * F]);
#pragma unroll
        for (int m = 0; m < 4; m++) {
            ulonglong2 a = w0[m], b = w1[m];
            o[2 * m]     = fma2(a.x, x0, o[2 * m]);
            o[2 * m]     = fma2(b.x, x1, o[2 * m]);
            o[2 * m + 1] = fma2(a.y, x0, o[2 * m + 1]);
            o[2 * m + 1] = fma2(b.y, x1, o[2 * m + 1]);
        }
    }
    float y[F];
#pragma unroll
    for (int j = 0; j < F / 2; j++) unpack2(o[j], y[2 * j], y[2 * j + 1]);
#pragma unroll
    for (int k = 0; k < F; k++) {
        g_nodes[(size_t)k * NN + n] = y[k];
    }
    if (out_nodes) {
#pragma unroll
        for (int k = 0; k < F; k++) out_nodes[(size_t)k * NN + n] = y[k];
    }

#pragma unroll
    for (int j = 0; j < HID / 4; j++) {
        ulonglong2 bv = *reinterpret_cast<const ulonglong2*>(&s_eb1[j * 4]);
        acc[2 * j] = bv.x; acc[2 * j + 1] = bv.y;
    }
#pragma unroll
    for (int k = 0; k < 16; k++) {
        ull xs = pack2(y[k], y[k]);
        const ulonglong2* w = reinterpret_cast<const ulonglong2*>(&s_ws[k * HID]);
#pragma unroll
        for (int m = 0; m < 16; m++) {
            ulonglong2 wv = w[m];
            acc[2 * m]     = fma2(wv.x, xs, acc[2 * m]);
            acc[2 * m + 1] = fma2(wv.y, xs, acc[2 * m + 1]);
        }
    }
    ull* outp = reinterpret_cast<ull*>(&g_ps[(size_t)n * HID]);
#pragma unroll
    for (int j = 0; j < HID / 2; j++) outp[j] = acc[j];

#pragma unroll
    for (int j = 0; j < HID / 2; j++) acc[j] = 0ull;
#pragma unroll
    for (int k = 0; k < 16; k++) {
        ull xs = pack2(y[k], y[k]);
        const ulonglong2* w = reinterpret_cast<const ulonglong2*>(&s_wr[k * HID]);
#pragma unroll
        for (int m = 0; m < 16; m++) {
            ulonglong2 wv = w[m];
            acc[2 * m]     = fma2(wv.x, xs, acc[2 * m]);
            acc[2 * m + 1] = fma2(wv.y, xs, acc[2 * m + 1]);
        }
    }
    outp = reinterpret_cast<ull*>(&g_pr[(size_t)n * HID]);
#pragma unroll
    for (int j = 0; j < HID / 2; j++) outp[j] = acc[j];
}

// ---------------- edge MLP v6: v5 + linear weight loads + 72-stride ----------
#define ETPB 128
#define EPB  128
#define SG_STRIDE 72   // gather row: halves at +0 / +36; pair-stride = 16 banks (2-way max)
#define SX_STRIDE 34   // x row per PAIR: [k*2 + half]
#define SG_FLOATS (EPB * SG_STRIDE)
#define SX_FLOATS ((EPB / 2) * SX_STRIDE)
#define EDGE_SMEM_FLOATS (SG_FLOATS + SX_FLOATS + W1_FLOATS + W2_FLOATS + 16)

__global__ void __launch_bounds__(ETPB, 3)
edge_mlp_kernel(const float* src_fe, float* dst_fe,
                const int* __restrict__ snd, const int* __restrict__ rcv,
                int do_scatter) {
    extern __shared__ __align__(16) float smem[];
    float* s_g  = smem;                          // EPB x 72 (split halves)
    float* s_x  = s_g + SG_FLOATS;               // (EPB/2) x 34
    float* s_w1 = s_x + SX_FLOATS;               // 16 x 68 (split halves)
    float* s_w2 = s_w1 + W1_FLOATS;              // 1028 (split at 516)
    float* s_b2 = s_w2 + W2_FLOATS;              // 16

    const int tid  = threadIdx.x;
    const int half = tid & 1;                    // hidden half: h in [32*half, 32*half+32)
    const int pair = tid >> 1;                   // local pair index
    const int e0   = blockIdx.x * EPB;
    const int ee_l = tid & ~1;                   // even local edge of my pair
    const size_t em = (size_t)e0 + tid;          // my OUTPUT edge

    // ---- load my edge's features (coalesced) + indices, stage x into smem
    float x[16];
    if (src_fe) {
#pragma unroll
        for (int k = 0; k < 16; k++) x[k] = __ldcs(&src_fe[(size_t)k * EE + em]);
    } else {
#pragma unroll
        for (int q = 0; q < 4; q++) {
            float4 v = __ldcs(reinterpret_cast<const float4*>(&g_edges[em * F + q * 4]));
            x[q * 4] = v.x; x[q * 4 + 1] = v.y; x[q * 4 + 2] = v.z; x[q * 4 + 3] = v.w;
        }
    }
    const int s_me = snd[em];
    const int r_me = rcv[em];
#pragma unroll
    for (int k = 0; k < 16; k++) s_x[pair * SX_STRIDE + 2 * k + half] = x[k];

    // ---- weights: LINEAR float4 loads from pre-transposed globals (L2-hot)
    {
        const float4* w1s = reinterpret_cast<const float4*>(g_w1p);
        float4*       w1d = reinterpret_cast<float4*>(s_w1);
#pragma unroll
        for (int i = tid; i < W1_FLOATS / 4; i += ETPB) w1d[i] = w1s[i];
        const float4* w2s = reinterpret_cast<const float4*>(g_w2p);
        float4*       w2d = reinterpret_cast<float4*>(s_w2);
#pragma unroll
        for (int i = tid; i < W2_FLOATS / 4; i += ETPB) w2d[i] = w2s[i];
        if (tid < 16) s_b2[tid] = g_b2p[tid];
    }

    // ---- cooperative gather staging into split rows:
    //      chunk c (16B) -> word offset c*4 + (c>=8 ? 4 : 0)
    {
        const int wid  = tid >> 5;        // 4 warps, 32 edges each
        const int lane = tid & 31;
        const int sub  = lane >> 4;
        const int c    = lane & 15;
        const int coff = c * 4 + (c >= 8 ? 4 : 0);
#pragma unroll
        for (int i = 0; i < 32; i += 2) {
            int el = wid * 32 + i + sub;
            int s = snd[e0 + el];
            int r = rcv[e0 + el];
            ulonglong2 a = *reinterpret_cast<const ulonglong2*>(&g_ps[(size_t)s * HID + c * 4]);
            ulonglong2 b = *reinterpret_cast<const ulonglong2*>(&g_pr[(size_t)r * HID + c * 4]);
            ulonglong2 v; v.x = add2(a.x, b.x); v.y = add2(a.y, b.y);
            *reinterpret_cast<ulonglong2*>(&s_g[el * SG_STRIDE + coff]) = v;
        }
    }
    __syncthreads();

    // ---- layer-1 accumulators: my half of BOTH edges (eb1 folded in g_ps)
    ull acc0[16], acc1[16];   // acc0: edge ee_l, acc1: edge ee_l+1
    {
        const ulonglong2* g0 = reinterpret_cast<const ulonglong2*>(&s_g[ee_l * SG_STRIDE + half * 36]);
        const ulonglong2* g1 = reinterpret_cast<const ulonglong2*>(&s_g[(ee_l + 1) * SG_STRIDE + half * 36]);
#pragma unroll
        for (int m = 0; m < 8; m++) {
            ulonglong2 v = g0[m]; acc0[2 * m] = v.x; acc0[2 * m + 1] = v.y;
            ulonglong2 u = g1[m]; acc1[2 * m] = u.x; acc1[2 * m + 1] = u.y;
        }
    }

    // ---- layer 1: one LDS.64 per k gives both edges' x; weights shared
#pragma unroll
    for (int k = 0; k < 16; k++) {
        float2 xp = *reinterpret_cast<const float2*>(&s_x[pair * SX_STRIDE + 2 * k]);
        ull xs0 = pack2(xp.x, xp.x);     // edge ee_l
        ull xs1 = pack2(xp.y, xp.y);     // edge ee_l+1
        const ulonglong2* w = reinterpret_cast<const ulonglong2*>(&s_w1[k * 68 + half * 36]);
#pragma unroll
        for (int m = 0; m < 8; m++) {
            ulonglong2 wv = w[m];
            acc0[2 * m]     = fma2(wv.x, xs0, acc0[2 * m]);
            acc0[2 * m + 1] = fma2(wv.y, xs0, acc0[2 * m + 1]);
            acc1[2 * m]     = fma2(wv.x, xs1, acc1[2 * m]);
            acc1[2 * m + 1] = fma2(wv.y, xs1, acc1[2 * m + 1]);
        }
    }

    // ---- layer 2 partials over my 32 h (half 0 carries bias for BOTH edges)
    ull o0[8], o1[8];
    if (half == 0) {
#pragma unroll
        for (int j = 0; j < 4; j++) {
            ulonglong2 bv = *reinterpret_cast<const ulonglong2*>(&s_b2[j * 4]);
            o0[2 * j] = bv.x; o0[2 * j + 1] = bv.y;
            o1[2 * j] = bv.x; o1[2 * j + 1] = bv.y;
        }
    } else {
#pragma unroll
        for (int j = 0; j < 8; j++) { o0[j] = 0ull; o1[j] = 0ull; }
    }
    const float* w2b = s_w2 + (half ? 516 : 0);
#pragma unroll
    for (int it = 0; it < 16; it++) {
        float a0, a1; unpack2(acc0[it], a0, a1);
        a0 = fmaxf(a0, 0.f); a1 = fmaxf(a1, 0.f);
        ull p00 = pack2(a0, a0), p01 = pack2(a1, a1);
        float b0, b1; unpack2(acc1[it], b0, b1);
        b0 = fmaxf(b0, 0.f); b1 = fmaxf(b1, 0.f);
        ull p10 = pack2(b0, b0), p11 = pack2(b1, b1);
        const ulonglong2* w0 = reinterpret_cast<const ulonglong2*>(&w2b[(2 * it) * 16]);
        const ulonglong2* w1 = reinterpret_cast<const ulonglong2*>(&w2b[(2 * it + 1) * 16]);
#pragma unroll
        for (int m = 0; m < 4; m++) {
            ulonglong2 a = w0[m], b = w1[m];
            o0[2 * m]     = fma2(a.x, p00, o0[2 * m]);
            o0[2 * m]     = fma2(b.x, p01, o0[2 * m]);
            o0[2 * m + 1] = fma2(a.y, p00, o0[2 * m + 1]);
            o0[2 * m + 1] = fma2(b.y, p01, o0[2 * m + 1]);
            o1[2 * m]     = fma2(a.x, p10, o1[2 * m]);
            o1[2 * m]     = fma2(b.x, p11, o1[2 * m]);
            o1[2 * m + 1] = fma2(a.y, p10, o1[2 * m + 1]);
            o1[2 * m + 1] = fma2(b.y, p11, o1[2 * m + 1]);
        }
    }

    // ---- single exchange: send partner's-edge partial, receive mine
    float ov[16];
#pragma unroll
    for (int j = 0; j < 8; j++) {
        ull sel  = half ? o0[j] : o1[j];            // partial for PARTNER's edge
        ull rec  = __shfl_xor_sync(0xFFFFFFFFu, sel, 1);
        ull mine = half ? o1[j] : o0[j];            // my partial for MY edge
        ull tot  = add2(mine, rec);
        unpack2(tot, ov[2 * j], ov[2 * j + 1]);
    }

    // ---- write my edge's new features
    if (dst_fe) {
#pragma unroll
        for (int f = 0; f < F; f++) __stcs(&dst_fe[(size_t)f * EE + em], ov[f]);
    } else {
#pragma unroll
        for (int q = 0; q < 4; q++) {
            float4 v = make_float4(ov[q * 4], ov[q * 4 + 1], ov[q * 4 + 2], ov[q * 4 + 3]);
            __stcs(reinterpret_cast<float4*>(&g_edges[em * F + q * 4]), v);
        }
    }

    // ---- fused scatter into next round's aggregates
    if (do_scatter) {
        float* ps = &g_sent[(size_t)s_me * F];
        float* pr = &g_recv[(size_t)r_me * F];
#pragma unroll
        for (int f = 0; f < F; f += 4) {
            asm volatile("red.global.add.v4.f32 [%0], {%1,%2,%3,%4};"
                         :: "l"(ps + f), "f"(ov[f]), "f"(ov[f + 1]), "f"(ov[f + 2]), "f"(ov[f + 3])
                         : "memory");
            asm volatile("red.global.add.v4.f32 [%0], {%1,%2,%3,%4};"
                         :: "l"(pr + f), "f"(ov[f]), "f"(ov[f + 1]), "f"(ov[f + 2]), "f"(ov[f + 3])
                         : "memory");
        }
    }
}

extern "C" void kernel_launch(void* const* d_in, const int* in_sizes, int n_in,
                              void* d_out, int out_size) {
    const float* nodes     = (const float*)d_in[0];
    const float* edges     = (const float*)d_in[1];
    const int*   receivers = (const int*)  d_in[2];
    const int*   senders   = (const int*)  d_in[3];
    const float* nW1 = (const float*)d_in[4];
    const float* nb1 = (const float*)d_in[5];
    const float* nW2 = (const float*)d_in[6];
    const float* nb2 = (const float*)d_in[7];
    const float* eW1 = (const float*)d_in[8];
    const float* eb1 = (const float*)d_in[9];
    const float* eW2 = (const float*)d_in[10];
    const float* eb2 = (const float*)d_in[11];
    float* out_nodes = (float*)d_out;
    float* out_edges = (float*)d_out + (size_t)F * NN;

    const int EDGE_BLOCKS = EE / EPB;                  // 25000
    const int NODE_BLOCKS = (NN + 255) / 256;          // 391
    const int ZERO_BLOCKS = ((NN * F) / 4 + 255) / 256;
    const int EDGE_SMEM = EDGE_SMEM_FLOATS * 4;        // ~54.1 KB

    static int configured = 0;
    if (!configured) {
        cudaFuncSetAttribute(edge_mlp_kernel, cudaFuncAttributeMaxDynamicSharedMemorySize, EDGE_SMEM);
        configured = 1;
    }

    prep_weights_kernel<<<1, 128>>>(eW1, eW2, eb2);
    zero_agg_kernel<<<ZERO_BLOCKS, 256>>>();
    scatter_kernel<<<(EE + 255) / 256, 256>>>(edges, senders, receivers);

    for (int round = 0; round < ROUNDS; round++) {
        node_proj_kernel<<<NODE_BLOCKS, 256>>>(
            (round == 0) ? nodes : (const float*)0,
            (round == ROUNDS - 1) ? out_nodes : (float*)0,
            nW1, nb1, nW2, nb2, eW1, eb1);
        edge_mlp_kernel<<<EDGE_BLOCKS, ETPB, EDGE_SMEM>>>(
            (round == 0) ? edges : (const float*)0,
            (round == ROUNDS - 1) ? out_edges : (float*)0,
            senders, receivers, (round < ROUNDS - 1) ? 1 : 0);
    }
}

// round 10
// speedup vs baseline: 1.9214x; 1.0144x over previous
#include <cuda_runtime.h>

#define F   16
#define HID 64
#define NN  100000
#define EE  3200000
#define ROUNDS 5

typedef unsigned long long ull;

__device__ __align__(256) float g_edges[(size_t)EE * F];   // [E][F] internal layout
__device__ __align__(256) float g_nodes[F * NN];           // [F][N]
__device__ __align__(256) float g_sent[NN * F];            // [N][F]
__device__ __align__(256) float g_recv[NN * F];            // [N][F]
__device__ __align__(256) float g_ps[NN * HID];            // [N][HID]  eW1_s @ nodes + eb1
__device__ __align__(256) float g_pr[NN * HID];            // [N][HID]  eW1_r @ nodes

// pre-transposed edge-MLP weights (smem-layout-identical, loaded linearly)
#define W1_FLOATS (16 * 68)            // [k][68]: half0 h at k*68+h, half1 at k*68+4+h
#define W2_FLOATS (2 * 32 * 16 + 4)    // half0 rows at 0, half1 rows at 516
__device__ __align__(256) float g_w1p[W1_FLOATS];
__device__ __align__(256) float g_w2p[W2_FLOATS];
__device__ __align__(256) float g_b2p[16];

// pre-transposed node-MLP + projection weights
__device__ __align__(256) float g_nw1t[48 * HID];   // [k][h]
__device__ __align__(256) float g_nw2t[HID * F];    // [h][o]
__device__ __align__(256) float g_nws[16 * HID];    // eW1 cols 16..31, [k][h]
__device__ __align__(256) float g_nwr[16 * HID];    // eW1 cols 32..47, [k][h]
__device__ __align__(256) float g_nb1[HID];
__device__ __align__(256) float g_nb2[F];
__device__ __align__(256) float g_neb1[HID];

__device__ __forceinline__ ull pack2(float a, float b) {
    ull r; asm("mov.b64 %0, {%1,%2};" : "=l"(r) : "f"(a), "f"(b)); return r;
}
__device__ __forceinline__ void unpack2(ull v, float& a, float& b) {
    asm("mov.b64 {%0,%1}, %2;" : "=f"(a), "=f"(b) : "l"(v));
}
__device__ __forceinline__ ull fma2(ull a, ull b, ull c) {
    ull d; asm("fma.rn.f32x2 %0, %1, %2, %3;" : "=l"(d) : "l"(a), "l"(b), "l"(c)); return d;
}
__device__ __forceinline__ ull add2(ull a, ull b) {
    ull d; asm("add.rn.f32x2 %0, %1, %2;" : "=l"(d) : "l"(a), "l"(b)); return d;
}

// one-time: transpose ALL weights into kernel-friendly layouts
__global__ void prep_weights_kernel(const float* __restrict__ eW1,
                                    const float* __restrict__ eW2,
                                    const float* __restrict__ eb2,
                                    const float* __restrict__ nW1,
                                    const float* __restrict__ nb1,
                                    const float* __restrict__ nW2,
                                    const float* __restrict__ nb2,
                                    const float* __restrict__ eb1) {
    int tid = threadIdx.x;
    for (int i = tid; i < 16 * 64; i += blockDim.x) {
        int k = i >> 6, h = i & 63;
        g_w1p[k * 68 + h + (h >= 32 ? 4 : 0)] = eW1[h * 48 + k];
        g_nws[k * HID + h] = eW1[h * 48 + 16 + k];
        g_nwr[k * HID + h] = eW1[h * 48 + 32 + k];
    }
    for (int i = tid; i < 64 * 16; i += blockDim.x) {
        int h = i >> 4, o = i & 15;
        g_w2p[(h < 32) ? (h * 16 + o) : (516 + (h - 32) * 16 + o)] = eW2[o * 64 + h];
        g_nw2t[h * F + o] = nW2[o * HID + h];
    }
    for (int i = tid; i < 48 * 64; i += blockDim.x) {
        int k = i >> 6, h = i & 63;
        g_nw1t[k * HID + h] = nW1[h * 48 + k];
    }
    if (tid < 16) { g_b2p[tid] = eb2[tid]; g_nb2[tid] = nb2[tid]; }
    if (tid < HID) { g_nb1[tid] = nb1[tid]; g_neb1[tid] = eb1[tid]; }
}

__global__ void zero_agg_kernel() {
    int i = blockIdx.x * blockDim.x + threadIdx.x;
    const int n4 = (NN * F) / 4;
    float4 z = make_float4(0.f, 0.f, 0.f, 0.f);
    if (i < n4) {
        reinterpret_cast<float4*>(g_sent)[i] = z;
        reinterpret_cast<float4*>(g_recv)[i] = z;
    }
}

// round-0 scatter: reads the ORIGINAL [F][E] input edges
__global__ void scatter_kernel(const float* __restrict__ edges,
                               const int* __restrict__ snd, const int* __restrict__ rcv) {
    int e = blockIdx.x * blockDim.x + threadIdx.x;
    if (e >= EE) return;
    int s = snd[e];
    int r = rcv[e];
    float v[F];
#pragma unroll
    for (int f = 0; f < F; f++) v[f] = __ldcs(&edges[(size_t)f * EE + e]);
    float* ps = &g_sent[(size_t)s * F];
    float* pr = &g_recv[(size_t)r * F];
#pragma unroll
    for (int f = 0; f < F; f += 4) {
        asm volatile("red.global.add.v4.f32 [%0], {%1,%2,%3,%4};"
                     :: "l"(ps + f), "f"(v[f]), "f"(v[f + 1]), "f"(v[f + 2]), "f"(v[f + 3])
                     : "memory");
        asm volatile("red.global.add.v4.f32 [%0], {%1,%2,%3,%4};"
                     :: "l"(pr + f), "f"(v[f]), "f"(v[f + 1]), "f"(v[f + 2]), "f"(v[f + 3])
                     : "memory");
    }
}

// fused node MLP + edge projections + aggregate re-zeroing (prepped weights)
__global__ void __launch_bounds__(256)
node_proj_kernel(const float* src_nodes_in, float* out_nodes) {
    const float* __restrict__ src_nodes = src_nodes_in ? src_nodes_in : g_nodes;
    __shared__ __align__(16) float s_w1t[48 * HID];
    __shared__ __align__(16) float s_w2t[HID * F];
    __shared__ __align__(16) float s_ws[16 * HID];
    __shared__ __align__(16) float s_wr[16 * HID];
    __shared__ __align__(16) float s_b1[HID];
    __shared__ __align__(16) float s_b2[F];
    __shared__ __align__(16) float s_eb1[HID];
    {
        const float4* src;
        float4* dst;
        src = reinterpret_cast<const float4*>(g_nw1t); dst = reinterpret_cast<float4*>(s_w1t);
        for (int i = threadIdx.x; i < (48 * HID) / 4; i += blockDim.x) dst[i] = src[i];
        src = reinterpret_cast<const float4*>(g_nw2t); dst = reinterpret_cast<float4*>(s_w2t);
        for (int i = threadIdx.x; i < (HID * F) / 4; i += blockDim.x) dst[i] = src[i];
        src = reinterpret_cast<const float4*>(g_nws); dst = reinterpret_cast<float4*>(s_ws);
        for (int i = threadIdx.x; i < (16 * HID) / 4; i += blockDim.x) dst[i] = src[i];
        src = reinterpret_cast<const float4*>(g_nwr); dst = reinterpret_cast<float4*>(s_wr);
        for (int i = threadIdx.x; i < (16 * HID) / 4; i += blockDim.x) dst[i] = src[i];
        if (threadIdx.x < HID) { s_b1[threadIdx.x] = g_nb1[threadIdx.x]; s_eb1[threadIdx.x] = g_neb1[threadIdx.x]; }
        if (threadIdx.x < F)   s_b2[threadIdx.x] = g_nb2[threadIdx.x];
    }
    __syncthreads();

    int n = blockIdx.x * blockDim.x + threadIdx.x;
    if (n >= NN) return;

    ull acc[HID / 2];
#pragma unroll
    for (int j = 0; j < HID / 4; j++) {
        ulonglong2 bv = *reinterpret_cast<const ulonglong2*>(&s_b1[j * 4]);
        acc[2 * j] = bv.x; acc[2 * j + 1] = bv.y;
    }
#pragma unroll
    for (int k = 0; k < 16; k++) {
        float xk = src_nodes[(size_t)k * NN + n];
        ull xs = pack2(xk, xk);
        const ulonglong2* w = reinterpret_cast<const ulonglong2*>(&s_w1t[k * HID]);
#pragma unroll
        for (int m = 0; m < 16; m++) {
            ulonglong2 wv = w[m];
            acc[2 * m]     = fma2(wv.x, xs, acc[2 * m]);
            acc[2 * m + 1] = fma2(wv.y, xs, acc[2 * m + 1]);
        }
    }
    const float4 zero4 = make_float4(0.f, 0.f, 0.f, 0.f);
#pragma unroll
    for (int seg = 0; seg < 2; seg++) {
        float* aggr = seg == 0 ? &g_sent[(size_t)n * F] : &g_recv[(size_t)n * F];
        float xv[16];
#pragma unroll
        for (int q = 0; q < 4; q++) {
            float4 v = *reinterpret_cast<const float4*>(&aggr[q * 4]);
            xv[q * 4] = v.x; xv[q * 4 + 1] = v.y; xv[q * 4 + 2] = v.z; xv[q * 4 + 3] = v.w;
            *reinterpret_cast<float4*>(&aggr[q * 4]) = zero4;  // re-zero for next round
        }
#pragma unroll
        for (int k = 0; k < 16; k++) {
            ull xs = pack2(xv[k], xv[k]);
            const ulonglong2* w = reinterpret_cast<const ulonglong2*>(&s_w1t[((seg + 1) * 16 + k) * HID]);
#pragma unroll
            for (int m = 0; m < 16; m++) {
                ulonglong2 wv = w[m];
                acc[2 * m]     = fma2(wv.x, xs, acc[2 * m]);
                acc[2 * m + 1] = fma2(wv.y, xs, acc[2 * m + 1]);
            }
        }
    }

    ull o[F / 2];
#pragma unroll
    for (int j = 0; j < 4; j++) {
        ulonglong2 bv = *reinterpret_cast<const ulonglong2*>(&s_b2[j * 4]);
        o[2 * j] = bv.x; o[2 * j + 1] = bv.y;
    }
#pragma unroll
    for (int h = 0; h < HID; h += 2) {
        float h0, h1; unpack2(acc[h >> 1], h0, h1);
        h0 = fmaxf(h0, 0.f); h1 = fmaxf(h1, 0.f);
        ull x0 = pack2(h0, h0), x1 = pack2(h1, h1);
        const ulonglong2* w0 = reinterpret_cast<const ulonglong2*>(&s_w2t[h * F]);
        const ulonglong2* w1 = reinterpret_cast<const ulonglong2*>(&s_w2t[(h + 1) * F]);
#pragma unroll
        for (int m = 0; m < 4; m++) {
            ulonglong2 a = w0[m], b = w1[m];
            o[2 * m]     = fma2(a.x, x0, o[2 * m]);
            o[2 * m]     = fma2(b.x, x1, o[2 * m]);
            o[2 * m + 1] = fma2(a.y, x0, o[2 * m + 1]);
            o[2 * m + 1] = fma2(b.y, x1, o[2 * m + 1]);
        }
    }
    float y[F];
#pragma unroll
    for (int j = 0; j < F / 2; j++) unpack2(o[j], y[2 * j], y[2 * j + 1]);
#pragma unroll
    for (int k = 0; k < F; k++) {
        g_nodes[(size_t)k * NN + n] = y[k];
    }
    if (out_nodes) {
#pragma unroll
        for (int k = 0; k < F; k++) out_nodes[(size_t)k * NN + n] = y[k];
    }

#pragma unroll
    for (int j = 0; j < HID / 4; j++) {
        ulonglong2 bv = *reinterpret_cast<const ulonglong2*>(&s_eb1[j * 4]);
        acc[2 * j] = bv.x; acc[2 * j + 1] = bv.y;
    }
#pragma unroll
    for (int k = 0; k < 16; k++) {
        ull xs = pack2(y[k], y[k]);
        const ulonglong2* w = reinterpret_cast<const ulonglong2*>(&s_ws[k * HID]);
#pragma unroll
        for (int m = 0; m < 16; m++) {
            ulonglong2 wv = w[m];
            acc[2 * m]     = fma2(wv.x, xs, acc[2 * m]);
            acc[2 * m + 1] = fma2(wv.y, xs, acc[2 * m + 1]);
        }
    }
    ull* outp = reinterpret_cast<ull*>(&g_ps[(size_t)n * HID]);
#pragma unroll
    for (int j = 0; j < HID / 2; j++) outp[j] = acc[j];

#pragma unroll
    for (int j = 0; j < HID / 2; j++) acc[j] = 0ull;
#pragma unroll
    for (int k = 0; k < 16; k++) {
        ull xs = pack2(y[k], y[k]);
        const ulonglong2* w = reinterpret_cast<const ulonglong2*>(&s_wr[k * HID]);
#pragma unroll
        for (int m = 0; m < 16; m++) {
            ulonglong2 wv = w[m];
            acc[2 * m]     = fma2(wv.x, xs, acc[2 * m]);
            acc[2 * m + 1] = fma2(wv.y, xs, acc[2 * m + 1]);
        }
    }
    outp = reinterpret_cast<ull*>(&g_pr[(size_t)n * HID]);
#pragma unroll
    for (int j = 0; j < HID / 2; j++) outp[j] = acc[j];
}

// ---------------- edge MLP v7: v6 + cooperative smem red phase ---------------
#define ETPB 128
#define EPB  128
#define SG_STRIDE 72   // gather row: halves at +0 / +36; also reused as s_out (stride 20)
#define SX_STRIDE 34   // x row per PAIR: [k*2 + half]
#define SO_STRIDE 20   // ov row in reused s_g (16B-aligned rows, conflict-free phases)
#define SG_FLOATS (EPB * SG_STRIDE)
#define SX_FLOATS ((EPB / 2) * SX_STRIDE)
#define EDGE_SMEM_FLOATS (SG_FLOATS + SX_FLOATS + W1_FLOATS + W2_FLOATS + 16)

__global__ void __launch_bounds__(ETPB, 3)
edge_mlp_kernel(const float* src_fe, float* dst_fe,
                const int* __restrict__ snd, const int* __restrict__ rcv,
                int do_scatter) {
    extern __shared__ __align__(16) float smem[];
    float* s_g  = smem;                          // EPB x 72 (split halves); reused as s_out
    float* s_x  = s_g + SG_FLOATS;               // (EPB/2) x 34
    float* s_w1 = s_x + SX_FLOATS;               // 16 x 68 (split halves)
    float* s_w2 = s_w1 + W1_FLOATS;              // 1028 (split at 516)
    float* s_b2 = s_w2 + W2_FLOATS;              // 16

    const int tid  = threadIdx.x;
    const int half = tid & 1;                    // hidden half: h in [32*half, 32*half+32)
    const int pair = tid >> 1;                   // local pair index
    const int e0   = blockIdx.x * EPB;
    const int ee_l = tid & ~1;                   // even local edge of my pair
    const size_t em = (size_t)e0 + tid;          // my OUTPUT edge

    // ---- load my edge's features (coalesced), stage x into smem
    float x[16];
    if (src_fe) {
#pragma unroll
        for (int k = 0; k < 16; k++) x[k] = __ldcs(&src_fe[(size_t)k * EE + em]);
    } else {
#pragma unroll
        for (int q = 0; q < 4; q++) {
            float4 v = __ldcs(reinterpret_cast<const float4*>(&g_edges[em * F + q * 4]));
            x[q * 4] = v.x; x[q * 4 + 1] = v.y; x[q * 4 + 2] = v.z; x[q * 4 + 3] = v.w;
        }
    }
#pragma unroll
    for (int k = 0; k < 16; k++) s_x[pair * SX_STRIDE + 2 * k + half] = x[k];

    // ---- weights: LINEAR float4 loads from pre-transposed globals (L2-hot)
    {
        const float4* w1s = reinterpret_cast<const float4*>(g_w1p);
        float4*       w1d = reinterpret_cast<float4*>(s_w1);
        for (int i = tid; i < W1_FLOATS / 4; i += ETPB) w1d[i] = w1s[i];
        const float4* w2s = reinterpret_cast<const float4*>(g_w2p);
        float4*       w2d = reinterpret_cast<float4*>(s_w2);
        for (int i = tid; i < W2_FLOATS / 4; i += ETPB) w2d[i] = w2s[i];
        if (tid < 16) s_b2[tid] = g_b2p[tid];
    }

    // ---- cooperative gather staging into split rows
    {
        const int wid  = tid >> 5;        // 4 warps, 32 edges each
        const int lane = tid & 31;
        const int sub  = lane >> 4;
        const int c    = lane & 15;
        const int coff = c * 4 + (c >= 8 ? 4 : 0);
#pragma unroll
        for (int i = 0; i < 32; i += 2) {
            int el = wid * 32 + i + sub;
            int s = snd[e0 + el];
            int r = rcv[e0 + el];
            ulonglong2 a = *reinterpret_cast<const ulonglong2*>(&g_ps[(size_t)s * HID + c * 4]);
            ulonglong2 b = *reinterpret_cast<const ulonglong2*>(&g_pr[(size_t)r * HID + c * 4]);
            ulonglong2 v; v.x = add2(a.x, b.x); v.y = add2(a.y, b.y);
            *reinterpret_cast<ulonglong2*>(&s_g[el * SG_STRIDE + coff]) = v;
        }
    }
    __syncthreads();

    // ---- layer-1 accumulators: my half of BOTH edges (eb1 folded in g_ps)
    ull acc0[16], acc1[16];   // acc0: edge ee_l, acc1: edge ee_l+1
    {
        const ulonglong2* g0 = reinterpret_cast<const ulonglong2*>(&s_g[ee_l * SG_STRIDE + half * 36]);
        const ulonglong2* g1 = reinterpret_cast<const ulonglong2*>(&s_g[(ee_l + 1) * SG_STRIDE + half * 36]);
#pragma unroll
        for (int m = 0; m < 8; m++) {
            ulonglong2 v = g0[m]; acc0[2 * m] = v.x; acc0[2 * m + 1] = v.y;
            ulonglong2 u = g1[m]; acc1[2 * m] = u.x; acc1[2 * m + 1] = u.y;
        }
    }

    // ---- layer 1: one LDS.64 per k gives both edges' x; weights shared
#pragma unroll
    for (int k = 0; k < 16; k++) {
        float2 xp = *reinterpret_cast<const float2*>(&s_x[pair * SX_STRIDE + 2 * k]);
        ull xs0 = pack2(xp.x, xp.x);     // edge ee_l
        ull xs1 = pack2(xp.y, xp.y);     // edge ee_l+1
        const ulonglong2* w = reinterpret_cast<const ulonglong2*>(&s_w1[k * 68 + half * 36]);
#pragma unroll
        for (int m = 0; m < 8; m++) {
            ulonglong2 wv = w[m];
            acc0[2 * m]     = fma2(wv.x, xs0, acc0[2 * m]);
            acc0[2 * m + 1] = fma2(wv.y, xs0, acc0[2 * m + 1]);
            acc1[2 * m]     = fma2(wv.x, xs1, acc1[2 * m]);
            acc1[2 * m + 1] = fma2(wv.y, xs1, acc1[2 * m + 1]);
        }
    }

    // ---- layer 2 partials over my 32 h (half 0 carries bias for BOTH edges)
    ull o0[8], o1[8];
    if (half == 0) {
#pragma unroll
        for (int j = 0; j < 4; j++) {
            ulonglong2 bv = *reinterpret_cast<const ulonglong2*>(&s_b2[j * 4]);
            o0[2 * j] = bv.x; o0[2 * j + 1] = bv.y;
            o1[2 * j] = bv.x; o1[2 * j + 1] = bv.y;
        }
    } else {
#pragma unroll
        for (int j = 0; j < 8; j++) { o0[j] = 0ull; o1[j] = 0ull; }
    }
    const float* w2b = s_w2 + (half ? 516 : 0);
#pragma unroll
    for (int it = 0; it < 16; it++) {
        float a0, a1; unpack2(acc0[it], a0, a1);
        a0 = fmaxf(a0, 0.f); a1 = fmaxf(a1, 0.f);
        ull p00 = pack2(a0, a0), p01 = pack2(a1, a1);
        float b0, b1; unpack2(acc1[it], b0, b1);
        b0 = fmaxf(b0, 0.f); b1 = fmaxf(b1, 0.f);
        ull p10 = pack2(b0, b0), p11 = pack2(b1, b1);
        const ulonglong2* w0 = reinterpret_cast<const ulonglong2*>(&w2b[(2 * it) * 16]);
        const ulonglong2* w1 = reinterpret_cast<const ulonglong2*>(&w2b[(2 * it + 1) * 16]);
#pragma unroll
        for (int m = 0; m < 4; m++) {
            ulonglong2 a = w0[m], b = w1[m];
            o0[2 * m]     = fma2(a.x, p00, o0[2 * m]);
            o0[2 * m]     = fma2(b.x, p01, o0[2 * m]);
            o0[2 * m + 1] = fma2(a.y, p00, o0[2 * m + 1]);
            o0[2 * m + 1] = fma2(b.y, p01, o0[2 * m + 1]);
            o1[2 * m]     = fma2(a.x, p10, o1[2 * m]);
            o1[2 * m]     = fma2(b.x, p11, o1[2 * m]);
            o1[2 * m + 1] = fma2(a.y, p10, o1[2 * m + 1]);
            o1[2 * m + 1] = fma2(b.y, p11, o1[2 * m + 1]);
        }
    }

    // ---- single exchange: send partner's-edge partial, receive mine
    float ov[16];
#pragma unroll
    for (int j = 0; j < 8; j++) {
        ull sel  = half ? o0[j] : o1[j];            // partial for PARTNER's edge
        ull rec  = __shfl_xor_sync(0xFFFFFFFFu, sel, 1);
        ull mine = half ? o1[j] : o0[j];            // my partial for MY edge
        ull tot  = add2(mine, rec);
        unpack2(tot, ov[2 * j], ov[2 * j + 1]);
    }

    // ---- write my edge's new features
    if (dst_fe) {
#pragma unroll
        for (int f = 0; f < F; f++) __stcs(&dst_fe[(size_t)f * EE + em], ov[f]);
    } else {
#pragma unroll
        for (int q = 0; q < 4; q++) {
            float4 v = make_float4(ov[q * 4], ov[q * 4 + 1], ov[q * 4 + 2], ov[q * 4 + 3]);
            __stcs(reinterpret_cast<float4*>(&g_edges[em * F + q * 4]), v);
        }
    }

    // ---- cooperative red phase: 4 lanes cover one edge's 64B row -> 1 wavefront
    if (do_scatter) {
        float* s_out = s_g;                       // staging buffer is dead; reuse
        __syncthreads();                           // all acc-init reads of s_g done
#pragma unroll
        for (int q = 0; q < 4; q++) {
            float4 v = make_float4(ov[q * 4], ov[q * 4 + 1], ov[q * 4 + 2], ov[q * 4 + 3]);
            *reinterpret_cast<float4*>(&s_out[tid * SO_STRIDE + q * 4]) = v;
        }
        __syncthreads();
#pragma unroll
        for (int p = 0; p < 8; p++) {
            int g = tid + p * ETPB;
            int chunk = g & 3;
            int which = (g >> 2) & 1;
            int el    = g >> 3;
            int node  = which ? rcv[e0 + el] : snd[e0 + el];
            float* base = which ? g_recv : g_sent;
            float4 v = *reinterpret_cast<const float4*>(&s_out[el * SO_STRIDE + chunk * 4]);
            asm volatile("red.global.add.v4.f32 [%0], {%1,%2,%3,%4};"
                         :: "l"(base + (size_t)node * F + chunk * 4),
                            "f"(v.x), "f"(v.y), "f"(v.z), "f"(v.w)
                         : "memory");
        }
    }
}

extern "C" void kernel_launch(void* const* d_in, const int* in_sizes, int n_in,
                              void* d_out, int out_size) {
    const float* nodes     = (const float*)d_in[0];
    const float* edges     = (const float*)d_in[1];
    const int*   receivers = (const int*)  d_in[2];
    const int*   senders   = (const int*)  d_in[3];
    const float* nW1 = (const float*)d_in[4];
    const float* nb1 = (const float*)d_in[5];
    const float* nW2 = (const float*)d_in[6];
    const float* nb2 = (const float*)d_in[7];
    const float* eW1 = (const float*)d_in[8];
    const float* eb1 = (const float*)d_in[9];
    const float* eW2 = (const float*)d_in[10];
    const float* eb2 = (const float*)d_in[11];
    float* out_nodes = (float*)d_out;
    float* out_edges = (float*)d_out + (size_t)F * NN;

    const int EDGE_BLOCKS = EE / EPB;                  // 25000
    const int NODE_BLOCKS = (NN + 255) / 256;          // 391
    const int ZERO_BLOCKS = ((NN * F) / 4 + 255) / 256;
    const int EDGE_SMEM = EDGE_SMEM_FLOATS * 4;        // ~54.1 KB

    static int configured = 0;
    if (!configured) {
        cudaFuncSetAttribute(edge_mlp_kernel, cudaFuncAttributeMaxDynamicSharedMemorySize, EDGE_SMEM);
        configured = 1;
    }

    prep_weights_kernel<<<1, 256>>>(eW1, eW2, eb2, nW1, nb1, nW2, nb2, eb1);
    zero_agg_kernel<<<ZERO_BLOCKS, 256>>>();
    scatter_kernel<<<(EE + 255) / 256, 256>>>(edges, senders, receivers);

    for (int round = 0; round < ROUNDS; round++) {
        node_proj_kernel<<<NODE_BLOCKS, 256>>>(
            (round == 0) ? nodes : (const float*)0,
            (round == ROUNDS - 1) ? out_nodes : (float*)0);
        edge_mlp_kernel<<<EDGE_BLOCKS, ETPB, EDGE_SMEM>>>(
            (round == 0) ? edges : (const float*)0,
            (round == ROUNDS - 1) ? out_edges : (float*)0,
            senders, receivers, (round < ROUNDS - 1) ? 1 : 0);
    }
}